// round 11
// baseline (speedup 1.0000x reference)
#include <cuda_runtime.h>
#include <cstdint>

// ---------------------------------------------------------------------------
// Problem constants
// ---------------------------------------------------------------------------
#define BB 64
#define CC 3
#define HH 384
#define WW 384
#define HW (HH * WW)              // 147456
#define CHW (CC * HW)             // 442368
#define NTOT (BB * CHW)           // 28311552
// float4 granularity
#define F4_PER_ROW (WW / 4)       // 96
#define F4_PER_CH  (HW / 4)       // 36864
#define F4_PER_IMG (CHW / 4)      // 110592
#define NF4        (NTOT / 4)     // 7077888
// tiling: block = 256 threads; tile = 1024 float4 (16KB); 12 tiles per block
#define BLK        256
#define TILE_F4    1024
#define TPB        12             // tiles per block
#define NBLK       (NF4 / (TILE_F4 * TPB))   // 576 blocks, exact
#define BLOCKS_PER_IMG (F4_PER_IMG / (TILE_F4 * TPB))  // 9, exact
#define STAGES     3

// ---------------------------------------------------------------------------
// constexpr threefry2x32 (JAX schedule) — compile-time child keys of
// jax.random.split(jax.random.key(42), 6), partitionable: child i = tf(k,0,i)
// ---------------------------------------------------------------------------
constexpr unsigned long long tf_pair_ce(unsigned k0, unsigned k1,
                                        unsigned x0, unsigned x1) {
    unsigned k2 = k0 ^ k1 ^ 0x1BD11BDAu;
    x0 += k0; x1 += k1;
    const int rots[5][4] = {{13,15,26,6},{17,29,16,24},{13,15,26,6},
                            {17,29,16,24},{13,15,26,6}};
    const unsigned ka[5] = {k1, k2, k0, k1, k2};
    const unsigned kb[5] = {k2, k0, k1, k2, k0};
    for (int g = 0; g < 5; ++g) {
        for (int j = 0; j < 4; ++j) {
            x0 += x1;
            int r = rots[g][j];
            x1 = (x1 << r) | (x1 >> (32 - r));
            x1 ^= x0;
        }
        x0 += ka[g];
        x1 += kb[g] + (unsigned)(g + 1);
    }
    return ((unsigned long long)x0 << 32) | (unsigned long long)x1;
}

constexpr unsigned long long KP_ = tf_pair_ce(0u, 42u, 0u, 0u);
constexpr unsigned long long KA_ = tf_pair_ce(0u, 42u, 0u, 1u);
constexpr unsigned long long KR_ = tf_pair_ce(0u, 42u, 0u, 2u);
constexpr unsigned long long KT_ = tf_pair_ce(0u, 42u, 0u, 3u);
constexpr unsigned long long KL_ = tf_pair_ce(0u, 42u, 0u, 4u);
constexpr unsigned long long KN_ = tf_pair_ce(0u, 42u, 0u, 5u);

#define KHI(k) ((unsigned)((k) >> 32))
#define KLO(k) ((unsigned)((k) & 0xFFFFFFFFull))

// ---------------------------------------------------------------------------
// Device threefry: bits(i) = out0 ^ out1 of threefry(key, 0, i)
// ---------------------------------------------------------------------------
__device__ __forceinline__ unsigned tf_bits(unsigned k0, unsigned k1, unsigned ctr) {
    unsigned k2 = k0 ^ k1 ^ 0x1BD11BDAu;
    unsigned x0 = k0;
    unsigned x1 = ctr + k1;
#define TFR(r) { x0 += x1; x1 = __funnelshift_l(x1, x1, (r)); x1 ^= x0; }
    TFR(13) TFR(15) TFR(26) TFR(6)
    x0 += k1; x1 += k2 + 1u;
    TFR(17) TFR(29) TFR(16) TFR(24)
    x0 += k2; x1 += k0 + 2u;
    TFR(13) TFR(15) TFR(26) TFR(6)
    x0 += k0; x1 += k1 + 3u;
    TFR(17) TFR(29) TFR(16) TFR(24)
    x0 += k1; x1 += k2 + 4u;
    TFR(13) TFR(15) TFR(26) TFR(6)
    x0 += k2; x1 += k0 + 5u;
#undef TFR
    return x0 ^ x1;
}

__device__ __forceinline__ float u01(unsigned bits) {
    return __uint_as_float((bits >> 9) | 0x3F800000u) - 1.0f;
}

// ---------------------------------------------------------------------------
// Per-sample erase rectangle {top, bottom, left, right}; empty when invalid.
// Same arithmetic as the reference -> bit-identical decisions.
// ---------------------------------------------------------------------------
__device__ __forceinline__ int4 compute_rect(int b) {
    float up = u01(tf_bits(KHI(KP_), KLO(KP_), (unsigned)b));
    bool apply = (up <= 0.5f);

    float ua = u01(tf_bits(KHI(KA_), KLO(KA_), (unsigned)b));
    const float RA = 0.33f - 0.02f;
    float ta_u = fmaxf(0.02f, __fadd_rn(__fmul_rn(ua, RA), 0.02f));
    float ta = __fmul_rn(ta_u, 147456.0f);

    float ur = u01(tf_bits(KHI(KR_), KLO(KR_), (unsigned)b));
    const float RR = 3.3f - 0.3f;
    float ar = fmaxf(0.3f, __fadd_rn(__fmul_rn(ur, RR), 0.3f));

    int h_e = (int)rintf(__fsqrt_rn(__fmul_rn(ta, ar)));
    int w_e = (int)rintf(__fsqrt_rn(__fdiv_rn(ta, ar)));

    bool valid = apply && (h_e < HH) && (w_e < WW);

    float ut = u01(tf_bits(KHI(KT_), KLO(KT_), (unsigned)b));
    float ul = u01(tf_bits(KHI(KL_), KLO(KL_), (unsigned)b));
    int top  = (int)floorf(__fmul_rn(ut, (float)(HH - h_e + 1)));
    int left = (int)floorf(__fmul_rn(ul, (float)(WW - w_e + 1)));

    int4 r;
    if (valid) { r.x = top; r.y = top + h_e; r.z = left; r.w = left + w_e; }
    else       { r.x = 0;   r.y = 0;         r.z = 0;    r.w = 0; }
    return r;
}

// ---------------------------------------------------------------------------
// Noise at global element index i (JAX normal = sqrt(2)*erfinv(uniform(-1,1)))
// ---------------------------------------------------------------------------
__device__ __forceinline__ float noise_at(unsigned i) {
    unsigned bits = tf_bits(KHI(KN_), KLO(KN_), i);
    float u = u01(bits);
    const float LO = -0.99999994039535522461f;    // nextafter(-1,0) f32
    float v = fmaxf(LO, __fadd_rn(__fmul_rn(u, 2.0f), LO));
    return __uint_as_float(0x3FB504F3u) * erfinvf(v);
}

// ---------------------------------------------------------------------------
// cp.async helpers (16B, L1-bypass) — per-thread private pipeline
// ---------------------------------------------------------------------------
__device__ __forceinline__ void cp16(void* smem_dst, const void* gmem_src) {
    unsigned s = (unsigned)__cvta_generic_to_shared(smem_dst);
    asm volatile("cp.async.cg.shared.global [%0], [%1], 16;\n"
                 :: "r"(s), "l"(gmem_src) : "memory");
}
__device__ __forceinline__ void cp_commit() {
    asm volatile("cp.async.commit_group;\n" ::: "memory");
}
__device__ __forceinline__ void cp_wait2() {
    asm volatile("cp.async.wait_group 2;\n" ::: "memory");
}

// ---------------------------------------------------------------------------
// Streaming kernel with a per-thread 3-stage cp.async pipeline.
// Block covers 12 tiles x 1024 float4 = 49152 floats; 9 blocks per image
// (exact), so the erase rectangle is block-uniform. Each thread copies and
// consumes ONLY its own smem slots {j*256 + tid}, so no __syncthreads is
// needed: commit_group/wait_group order each thread's private pipeline.
// ---------------------------------------------------------------------------
__global__ void __launch_bounds__(BLK)
erase_kernel(const float4* __restrict__ x,
             const float* __restrict__ mean,
             const float* __restrict__ stdv,
             float4* __restrict__ out) {
    __shared__ float4 buf[STAGES][TILE_F4];     // 48KB exactly

    const int  t      = threadIdx.x;
    const int  b      = blockIdx.x / BLOCKS_PER_IMG;      // image (uniform)
    const int  ib     = blockIdx.x - b * BLOCKS_PER_IMG;  // block within image
    const unsigned blk_f4 = (unsigned)blockIdx.x * (TILE_F4 * TPB);
    const unsigned img_f4 = (unsigned)ib * (TILE_F4 * TPB); // offset in image

    // per-thread (redundant, once per block) rect + channel constants
    int4 rc = compute_rect(b);
    float iv0 = 1.0f / __ldg(&stdv[0]);
    float iv1 = 1.0f / __ldg(&stdv[1]);
    float iv2 = 1.0f / __ldg(&stdv[2]);
    float bs0 = -__ldg(&mean[0]) * iv0;
    float bs1 = -__ldg(&mean[1]) * iv1;
    float bs2 = -__ldg(&mean[2]) * iv2;

    const float4* xb = x + blk_f4 + t;

    // prologue: prefetch tiles 0 and 1
    #pragma unroll
    for (int s = 0; s < STAGES - 1; ++s) {
        #pragma unroll
        for (int j = 0; j < 4; ++j)
            cp16(&buf[s][j * 256 + t], xb + s * TILE_F4 + j * 256);
        cp_commit();
    }

    for (int i = 0; i < TPB; ++i) {
        // prefetch tile i+2 (empty commit keeps group accounting uniform)
        if (i + STAGES - 1 < TPB) {
            int s = (i + STAGES - 1) % STAGES;
            #pragma unroll
            for (int j = 0; j < 4; ++j)
                cp16(&buf[s][j * 256 + t],
                     xb + (i + STAGES - 1) * TILE_F4 + j * 256);
        }
        cp_commit();
        cp_wait2();                 // tile i's data is now in smem

        const int s = i % STAGES;
        const unsigned loc0 = img_f4 + (unsigned)i * TILE_F4 + (unsigned)t;

        #pragma unroll
        for (int j = 0; j < 4; ++j) {
            unsigned loc = loc0 + (unsigned)j * 256u;     // float4 idx in image
            float4 v = buf[s][j * 256 + t];

            // decode (c, h, w0) for this float4
            unsigned c  = loc / (unsigned)F4_PER_CH;
            unsigned r0 = loc - c * (unsigned)F4_PER_CH;
            unsigned h  = r0 / (unsigned)F4_PER_ROW;
            int      w0 = (int)(r0 - h * (unsigned)F4_PER_ROW) * 4;

            float inv  = (c == 0u) ? iv0 : ((c == 1u) ? iv1 : iv2);
            float bias = (c == 0u) ? bs0 : ((c == 1u) ? bs1 : bs2);

            v.x = fmaf(v.x, inv, bias);
            v.y = fmaf(v.y, inv, bias);
            v.z = fmaf(v.z, inv, bias);
            v.w = fmaf(v.w, inv, bias);

            int hi = (int)h;
            if (hi >= rc.x && hi < rc.y && w0 + 3 >= rc.z && w0 < rc.w) {
                unsigned e = ((unsigned)b * (unsigned)F4_PER_IMG + loc) * 4u;
                if (w0 + 0 >= rc.z && w0 + 0 < rc.w) v.x = noise_at(e + 0u);
                if (w0 + 1 >= rc.z && w0 + 1 < rc.w) v.y = noise_at(e + 1u);
                if (w0 + 2 >= rc.z && w0 + 2 < rc.w) v.z = noise_at(e + 2u);
                if (w0 + 3 >= rc.z && w0 + 3 < rc.w) v.w = noise_at(e + 3u);
            }

            out[blk_f4 + (unsigned)i * TILE_F4 + (unsigned)j * 256u + (unsigned)t] = v;
        }
    }
}

// ---------------------------------------------------------------------------
// Launch
// ---------------------------------------------------------------------------
extern "C" void kernel_launch(void* const* d_in, const int* in_sizes, int n_in,
                              void* d_out, int out_size) {
    const float4* x   = (const float4*)d_in[0];
    const float*  mn  = (const float*)d_in[1];
    const float*  sd  = (const float*)d_in[2];
    float4*       out = (float4*)d_out;

    erase_kernel<<<NBLK, BLK>>>(x, mn, sd, out);
}